// round 17
// baseline (speedup 1.0000x reference)
#include <cuda_runtime.h>
#include <cuda_bf16.h>
#include <math.h>
#include <cstdint>

// Problem dims
#define Bv 128
#define Tv 1024
#define Iv 512
#define Hv 1024
#define Ov 256

#define NBLK_SCAN 128   // 4 domains x 32 CTAs (kc16 x nt2 each)
#define KCHUNKS   16
#define NDOM      4
#define DOM_CTAS  32

typedef unsigned long long ull;

// -------- scratch (device globals: no allocation allowed) --------
__device__ __nv_bfloat16 g_xh[(size_t)Tv * Bv * Iv]; // x split hi, [t][b][i]
__device__ __nv_bfloat16 g_xl[(size_t)Tv * Bv * Iv]; // x split lo, [t][b][i]
__device__ __nv_bfloat16 g_hh[Bv * Hv];              // hidden state, bf16 hi
__device__ __nv_bfloat16 g_hl[Bv * Hv];              // hidden state, bf16 lo
__device__ float g_part[KCHUNKS][Bv * Hv];           // split-K partials (8 MB)
__device__ unsigned g_cnt4[NDOM * 32];               // per-domain arrival counters
__device__ unsigned g_gen4[NDOM * 32];               // per-domain release words

// -------- per-domain monotonic barrier (tid0-only) --------
__device__ __forceinline__ void bar_arrive(int d, unsigned gen0, unsigned n) {
    asm volatile("fence.acq_rel.gpu;" ::: "memory");
    unsigned prev;
    asm volatile("atom.relaxed.gpu.global.add.u32 %0, [%1], 1;"
                 : "=r"(prev) : "l"(&g_cnt4[d * 32]) : "memory");
    if ((prev & 31u) == 31u) {   // 32nd arrival of instance n in this domain
        asm volatile("st.release.gpu.u32 [%0], %1;"
                     :: "l"(&g_gen4[d * 32]), "r"(gen0 + n) : "memory");
    }
}
__device__ __forceinline__ void bar_wait(int d, unsigned gen0, unsigned n) {
    unsigned cur;
    do {
        asm volatile("ld.acquire.gpu.u32 %0, [%1];"
                     : "=r"(cur) : "l"(&g_gen4[d * 32]) : "memory");
    } while ((cur - gen0) < n);
}

// -------- mma.sync / ldmatrix helpers --------
__device__ __forceinline__ uint32_t smem_u32(const void* p) {
    uint32_t a;
    asm("{ .reg .u64 t; cvta.to.shared.u64 t, %1; cvt.u32.u64 %0, t; }"
        : "=r"(a) : "l"(p));
    return a;
}
__device__ __forceinline__ void ldsm4(uint32_t r[4], uint32_t addr) {
    asm volatile("ldmatrix.sync.aligned.m8n8.x4.shared.b16 {%0,%1,%2,%3}, [%4];"
                 : "=r"(r[0]), "=r"(r[1]), "=r"(r[2]), "=r"(r[3]) : "r"(addr));
}
__device__ __forceinline__ void mma_bf16(float d[4], const uint32_t a[4],
                                         const uint32_t b0, const uint32_t b1) {
    asm volatile(
        "mma.sync.aligned.m16n8k16.row.col.f32.bf16.bf16.f32 "
        "{%0,%1,%2,%3}, {%4,%5,%6,%7}, {%8,%9}, {%0,%1,%2,%3};"
        : "+f"(d[0]), "+f"(d[1]), "+f"(d[2]), "+f"(d[3])
        : "r"(a[0]), "r"(a[1]), "r"(a[2]), "r"(a[3]), "r"(b0), "r"(b1));
}
__device__ __forceinline__ uint32_t bf16pack(float a, float b) {
    __nv_bfloat16 x = __float2bfloat16(a);
    __nv_bfloat16 y = __float2bfloat16(b);
    return (uint32_t)__bfloat16_as_ushort(x) |
           ((uint32_t)__bfloat16_as_ushort(y) << 16);
}

// ============================================================
// Kernel 0: split x into bf16 hi/lo, transpose [b][t][i] -> [t][b][i]
// ============================================================
__global__ void __launch_bounds__(256) split_x(const float* __restrict__ X)
{
    size_t idx8 = (size_t)blockIdx.x * 256 + threadIdx.x;
    if (idx8 >= (size_t)Bv * Tv * Iv / 8) return;
    int i = (int)(idx8 & 63) * 8;
    int t = (int)((idx8 >> 6) & 1023);
    int b = (int)(idx8 >> 16);

    const float* src = X + (((size_t)b * Tv + t) * Iv + i);
    float4 f0 = *(const float4*)(src + 0);
    float4 f1 = *(const float4*)(src + 4);
    float f[8] = {f0.x, f0.y, f0.z, f0.w, f1.x, f1.y, f1.z, f1.w};

    uint32_t hi[4], lo[4];
#pragma unroll
    for (int j = 0; j < 4; j++) {
        __nv_bfloat16 h0 = __float2bfloat16(f[2 * j]);
        __nv_bfloat16 h1 = __float2bfloat16(f[2 * j + 1]);
        hi[j] = (uint32_t)__bfloat16_as_ushort(h0) |
                ((uint32_t)__bfloat16_as_ushort(h1) << 16);
        lo[j] = bf16pack(f[2 * j] - __bfloat162float(h0),
                         f[2 * j + 1] - __bfloat162float(h1));
    }
    size_t o = (((size_t)t * Bv + b) * Iv + i);
    *(uint4*)&g_xh[o] = *(const uint4*)hi;
    *(uint4*)&g_xl[o] = *(const uint4*)lo;
}

// ============================================================
// Kernel B: persistent fused scan, 4 independent batch domains.
// Domain d (32 batch rows): 32 CTAs (kc16 x nt2), CTA tile 32M x 512N,
// rec K=64 (128B-row tiles) + x K=32 (64B-row tiles), 3-term bf16 split,
// x-GEMM in bar1's wait shadow.
// SMEM 208KB:
//   Ahh 4K | Ahl 4K           (h: 32 rows x 128B)
//   Bwh 64K | Bwl 64K         (Wr: 512n x 128B)
//   Kwh 32K | Kwl 32K         (Wk: 512n x 64B, (row&3)<<4 swizzle)
//   Xhh 2x2K | Xhl 2x2K       (x: 32 rows x 64B, double-buffered)
// ============================================================
__global__ void __launch_bounds__(256, 1) scan_kernel(
    const float* __restrict__ WR, const float* __restrict__ WK,
    const float* __restrict__ bias)
{
    extern __shared__ __align__(1024) char smem[];
    char* sAhh = smem;                     // 4096
    char* sAhl = smem + 4096;              // 4096
    char* sBwh = smem + 8192;              // 65536
    char* sBwl = smem + 73728;             // 65536
    char* sKwh = smem + 139264;            // 32768
    char* sKwl = smem + 172032;            // 32768
    char* sXhh = smem + 204800;            // 2 bufs x 2048
    char* sXhl = smem + 208896;            // 2 bufs x 2048
    const uint32_t pAhh = smem_u32(smem);
    const uint32_t pAhl = pAhh + 4096;
    const uint32_t pBwh = pAhh + 8192;
    const uint32_t pBwl = pAhh + 73728;
    const uint32_t pKwh = pAhh + 139264;
    const uint32_t pKwl = pAhh + 172032;
    const uint32_t pXhh = pAhh + 204800;
    const uint32_t pXhl = pAhh + 208896;

    const int tid = threadIdx.x;
    const int wid = tid >> 5;
    const int lid = tid & 31;
    const int bi = blockIdx.x;
    const int d  = bi >> 5;            // domain 0..3
    const int ib = bi & 31;            // CTA within domain
    const int kc = ib >> 1;            // 0..15
    const int nt = ib & 1;             // 0..1
    const int kbase = kc * 64;         // Wr K slice
    const int xbase = kc * 32;         // Wk K slice
    const int nbase = nt * 512;        // N base (512 cols/CTA)
    const int mrow0 = d * 32;          // global batch-row base
    // reduce ownership: CTA owns global h row (d*32 + ib), cols tid*4..+4
    const size_t e = (size_t)(mrow0 + ib) * Hv + tid * 4;

    const int wm = wid & 1;            // M: 2 warps x 16
    const int wn = wid >> 1;           // N: 4 warps x 128

    // ldmatrix lane invariants
    const int rowA = ((lid >> 3) & 1) * 8 + (lid & 7);
    const int khA  = (lid >> 4) * 16;
    const int rowB = ((lid >> 4) & 1) * 8 + (lid & 7);
    const int khB  = ((lid >> 3) & 1) * 16;
    const int sw   = (lid & 7) << 4;   // 128B-row tiles
    const int swx  = (lid & 3) << 4;   // 64B-row tiles (row&3 == lid&3)
    const uint32_t aHiBase = pAhh + (wm * 16 + rowA) * 128;
    const uint32_t aLoBase = pAhl + (wm * 16 + rowA) * 128;
    const uint32_t bHiBase = pBwh + (wn * 128 + rowB) * 128;  // np stride 2048
    const uint32_t bLoBase = pBwl + (wn * 128 + rowB) * 128;
    const uint32_t kHiBase = pKwh + (wn * 128 + rowB) * 64;   // np stride 1024
    const uint32_t kLoBase = pKwl + (wn * 128 + rowB) * 64;
    const uint32_t xHiBase = pXhh + (wm * 16 + rowA) * 64;    // + buf*2048
    const uint32_t xLoBase = pXhl + (wm * 16 + rowA) * 64;

    // domain barrier baseline
    unsigned gen0 = 0;
    if (tid == 0) {
        asm volatile("ld.relaxed.gpu.u32 %0, [%1];"
                     : "=r"(gen0) : "l"(&g_gen4[d * 32]));
    }

    // ---- preload Wr slice: [n 0..511][k 0..63], 128B rows, swizzled ----
    for (int idx = tid; idx < 512 * 64; idx += 256) {
        int n = idx & 511;
        int k = idx >> 9;
        float w = WR[(size_t)(kbase + k) * Hv + nbase + n];
        __nv_bfloat16 wh = __float2bfloat16(w);
        __nv_bfloat16 wl = __float2bfloat16(w - __bfloat162float(wh));
        uint32_t off = n * 128 + ((k * 2) ^ ((n & 7) << 4));
        *(__nv_bfloat16*)(sBwh + off) = wh;
        *(__nv_bfloat16*)(sBwl + off) = wl;
    }
    // ---- preload Wk slice: [n 0..511][k 0..31], 64B rows, (n&3)<<4 swizzle ----
    for (int idx = tid; idx < 512 * 32; idx += 256) {
        int n = idx & 511;
        int k = idx >> 9;
        float w = WK[(size_t)(xbase + k) * Hv + nbase + n];
        __nv_bfloat16 wh = __float2bfloat16(w);
        __nv_bfloat16 wl = __float2bfloat16(w - __bfloat162float(wh));
        uint32_t off = n * 64 + ((k * 2) ^ ((n & 3) << 4));
        *(__nv_bfloat16*)(sKwh + off) = wh;
        *(__nv_bfloat16*)(sKwl + off) = wl;
    }

    // zero initial hidden state (this CTA's row)
    *(ull*)&g_hh[e] = 0ull;
    *(ull*)&g_hl[e] = 0ull;

    float4 bb = *(const float4*)&bias[tid * 4];

    // staging geometry
    // h tile: 32 rows x 128B, 8 threads/row, 16B each
    const int hrow = tid >> 3;
    const uint32_t hoff = (uint32_t)(tid & 7) * 16;
    const uint32_t hsw = (uint32_t)(hrow & 7) << 4;
    // x tile: 32 rows x 64B, threads 0..127, 4/row, 16B each
    const int xrow = tid >> 2;                 // valid when tid < 128
    const uint32_t xoff = (uint32_t)(tid & 3) * 16;
    const uint32_t xsw = (uint32_t)(xrow & 3) << 4;

    // ---- stage x[0] into buf 0 ----
    if (tid < 128) {
        const char* xh = (const char*)(g_xh + (size_t)(mrow0 + xrow) * Iv + xbase) + xoff;
        const char* xl = (const char*)(g_xl + (size_t)(mrow0 + xrow) * Iv + xbase) + xoff;
        uint4 a = __ldcg((const uint4*)xh);
        uint4 b = __ldcg((const uint4*)xl);
        *(uint4*)(sXhh + xrow * 64 + (xoff ^ xsw)) = a;
        *(uint4*)(sXhl + xrow * 64 + (xoff ^ xsw)) = b;
    }
    __syncthreads();

    float D[16][4];

    // ---- prologue: D = x[0] @ Wk ----
#pragma unroll
    for (int j = 0; j < 16; j++)
#pragma unroll
        for (int q = 0; q < 4; q++) D[j][q] = 0.f;
#pragma unroll
    for (int ks = 0; ks < 2; ks++) {
        const uint32_t koffA = ((ks * 32) | khA) ^ swx;
        const uint32_t koffB = ((ks * 32) | khB) ^ swx;
        uint32_t Ah[4], Al[4];
        ldsm4(Ah, xHiBase + koffA);
        ldsm4(Al, xLoBase + koffA);
#pragma unroll
        for (int np = 0; np < 8; np++) {
            uint32_t Bh[4], Bl[4];
            ldsm4(Bh, kHiBase + np * 1024 + koffB);
            ldsm4(Bl, kLoBase + np * 1024 + koffB);
#pragma unroll
            for (int h2 = 0; h2 < 2; h2++) {
                const int q = h2 * 2;
                mma_bf16(D[np * 2 + h2], Ah, Bh[q], Bh[q + 1]);
                mma_bf16(D[np * 2 + h2], Al, Bh[q], Bh[q + 1]);
                mma_bf16(D[np * 2 + h2], Ah, Bl[q], Bl[q + 1]);
            }
        }
    }

    // ---- initial domain barrier (instance 1) ----
    __syncthreads();
    if (tid == 0) { bar_arrive(d, gen0, 1u); bar_wait(d, gen0, 1u); }
    __syncthreads();

#pragma unroll 1
    for (int t = 0; t < Tv; t++) {
        const unsigned n1 = 2u + 2u * (unsigned)t;
        const unsigned n2 = 3u + 2u * (unsigned)t;

        // ---- stage h slice: 32 rows x 64k (bf16 hi/lo, swizzled) ----
        {
            const char* sh = (const char*)(g_hh + (size_t)(mrow0 + hrow) * Hv + kbase) + hoff;
            const char* sl = (const char*)(g_hl + (size_t)(mrow0 + hrow) * Hv + kbase) + hoff;
            uint4 a = __ldcg((const uint4*)sh);
            uint4 b = __ldcg((const uint4*)sl);
            *(uint4*)(sAhh + hrow * 128 + (hoff ^ hsw)) = a;
            *(uint4*)(sAhl + hrow * 128 + (hoff ^ hsw)) = b;
        }
        __syncthreads();

        // ---- rec-GEMM: D += h @ Wr (K=64, 4 ks, 3 terms) ----
#pragma unroll
        for (int ks = 0; ks < 4; ks++) {
            const uint32_t koffA = ((ks * 32) | khA) ^ sw;
            const uint32_t koffB = ((ks * 32) | khB) ^ sw;
            uint32_t Ah[4], Al[4];
            ldsm4(Ah, aHiBase + koffA);
            ldsm4(Al, aLoBase + koffA);
#pragma unroll
            for (int np = 0; np < 8; np++) {
                uint32_t Bh[4], Bl[4];
                ldsm4(Bh, bHiBase + np * 2048 + koffB);
                ldsm4(Bl, bLoBase + np * 2048 + koffB);
#pragma unroll
                for (int h2 = 0; h2 < 2; h2++) {
                    const int q = h2 * 2;
                    mma_bf16(D[np * 2 + h2], Ah, Bh[q], Bh[q + 1]);
                    mma_bf16(D[np * 2 + h2], Al, Bh[q], Bh[q + 1]);
                    mma_bf16(D[np * 2 + h2], Ah, Bl[q], Bl[q + 1]);
                }
            }
        }

        // ---- write split-K partials (global rows mrow0 + ...) ----
        {
            const int g = lid >> 2, c2 = (lid & 3) * 2;
            float* P = g_part[kc];
            int row0 = mrow0 + wm * 16 + g;
#pragma unroll
            for (int ntl = 0; ntl < 16; ntl++) {
                int col = nbase + wn * 128 + ntl * 8 + c2;
                float2 v0 = {D[ntl][0], D[ntl][1]};
                float2 v1 = {D[ntl][2], D[ntl][3]};
                *(float2*)&P[(size_t)row0 * Hv + col] = v0;
                *(float2*)&P[(size_t)(row0 + 8) * Hv + col] = v1;
            }
        }

        // ---- barrier 1: arrive early, x[t+1] work in the wait shadow ----
        __syncthreads();
        if (tid == 0) bar_arrive(d, gen0, n1);

        const uint32_t nbuf = (uint32_t)((t + 1) & 1) * 2048u;
        if (t + 1 < Tv && tid < 128) {
            const char* xh = (const char*)(g_xh + ((size_t)(t + 1) * Bv + mrow0 + xrow) * Iv + xbase) + xoff;
            const char* xl = (const char*)(g_xl + ((size_t)(t + 1) * Bv + mrow0 + xrow) * Iv + xbase) + xoff;
            uint4 a = __ldcg((const uint4*)xh);
            uint4 b = __ldcg((const uint4*)xl);
            *(uint4*)(sXhh + nbuf + xrow * 64 + (xoff ^ xsw)) = a;
            *(uint4*)(sXhl + nbuf + xrow * 64 + (xoff ^ xsw)) = b;
        }
        __syncthreads();   // sX[nbuf] visible CTA-wide

        // D = x[t+1] @ Wk  (independent of the domain barrier)
#pragma unroll
        for (int j = 0; j < 16; j++)
#pragma unroll
            for (int q = 0; q < 4; q++) D[j][q] = 0.f;
        if (t + 1 < Tv) {
#pragma unroll
            for (int ks = 0; ks < 2; ks++) {
                const uint32_t koffA = ((ks * 32) | khA) ^ swx;
                const uint32_t koffB = ((ks * 32) | khB) ^ swx;
                uint32_t Ah[4], Al[4];
                ldsm4(Ah, xHiBase + nbuf + koffA);
                ldsm4(Al, xLoBase + nbuf + koffA);
#pragma unroll
                for (int np = 0; np < 8; np++) {
                    uint32_t Bh[4], Bl[4];
                    ldsm4(Bh, kHiBase + np * 1024 + koffB);
                    ldsm4(Bl, kLoBase + np * 1024 + koffB);
#pragma unroll
                    for (int h2 = 0; h2 < 2; h2++) {
                        const int q = h2 * 2;
                        mma_bf16(D[np * 2 + h2], Ah, Bh[q], Bh[q + 1]);
                        mma_bf16(D[np * 2 + h2], Al, Bh[q], Bh[q + 1]);
                        mma_bf16(D[np * 2 + h2], Ah, Bl[q], Bl[q + 1]);
                    }
                }
            }
        }

        // deferred wait
        if (tid == 0) bar_wait(d, gen0, n1);
        __syncthreads();

        // ---- phase 2: reduce 16 partials + bias + tanh -> h (this CTA's row) ----
        {
            float4 s = bb;
#pragma unroll
            for (int c = 0; c < KCHUNKS; c++) {
                float4 p = __ldcg((const float4*)&g_part[c][e]);
                s.x += p.x; s.y += p.y; s.z += p.z; s.w += p.w;
            }
            float h[4] = {tanhf(s.x), tanhf(s.y), tanhf(s.z), tanhf(s.w)};
            unsigned short hh[4], hl[4];
#pragma unroll
            for (int j = 0; j < 4; j++) {
                __nv_bfloat16 a = __float2bfloat16(h[j]);
                __nv_bfloat16 b = __float2bfloat16(h[j] - __bfloat162float(a));
                hh[j] = __bfloat16_as_ushort(a);
                hl[j] = __bfloat16_as_ushort(b);
            }
            *(ull*)&g_hh[e] = *(const ull*)hh;
            *(ull*)&g_hl[e] = *(const ull*)hl;
        }

        // ---- barrier 2 ----
        __syncthreads();
        if (tid == 0) { bar_arrive(d, gen0, n2); bar_wait(d, gen0, n2); }
        __syncthreads();
    }
}

// ============================================================
// Kernel C: out[b][o] = h_last[b][:] @ fc_w[:, o] + fc_b[o]
// ============================================================
__global__ void __launch_bounds__(256, 1) fc_kernel(
    const float* __restrict__ fcw, const float* __restrict__ fcb,
    float* __restrict__ out)
{
    __shared__ float hs[Hv];
    const int b = blockIdx.x;
    for (int i = threadIdx.x; i < Hv; i += 256) {
        hs[i] = __bfloat162float(g_hh[(size_t)b * Hv + i]) +
                __bfloat162float(g_hl[(size_t)b * Hv + i]);
    }
    __syncthreads();

    const int o = threadIdx.x;
    float a0 = 0.f, a1 = 0.f, a2 = 0.f, a3 = 0.f;
#pragma unroll 4
    for (int k = 0; k < Hv; k += 4) {
        a0 = fmaf(hs[k + 0], fcw[(size_t)(k + 0) * Ov + o], a0);
        a1 = fmaf(hs[k + 1], fcw[(size_t)(k + 1) * Ov + o], a1);
        a2 = fmaf(hs[k + 2], fcw[(size_t)(k + 2) * Ov + o], a2);
        a3 = fmaf(hs[k + 3], fcw[(size_t)(k + 3) * Ov + o], a3);
    }
    out[(size_t)b * Ov + o] = (a0 + a1) + (a2 + a3) + fcb[o];
}

// ============================================================
extern "C" void kernel_launch(void* const* d_in, const int* in_sizes, int n_in,
                              void* d_out, int out_size)
{
    const float* x   = (const float*)d_in[0];
    const float* wk  = (const float*)d_in[1];
    const float* wr  = (const float*)d_in[2];
    const float* bs  = (const float*)d_in[3];
    const float* fcw = (const float*)d_in[4];
    const float* fcb = (const float*)d_in[5];
    float* out = (float*)d_out;

    static int smem_set = 0;
    if (!smem_set) {
        cudaFuncSetAttribute(scan_kernel,
                             cudaFuncAttributeMaxDynamicSharedMemorySize, 212992);
        smem_set = 1;
    }

    size_t nx8 = (size_t)Bv * Tv * Iv / 8;
    split_x<<<(unsigned)((nx8 + 255) / 256), 256>>>(x);
    scan_kernel<<<NBLK_SCAN, 256, 212992>>>(wr, wk, bs);
    fc_kernel<<<Bv, 256>>>(fcw, fcb, out);
}